// round 3
// baseline (speedup 1.0000x reference)
#include <cuda_runtime.h>
#include <math.h>

#define FEAT 128
#define HID  64
#define NMAX 50048
#define EMAX 1048576

// ---------------- scratch (static __device__, zero-initialized) ----------------
__device__ float g_h[NMAX * FEAT];     // post-GEMM features h
__device__ float g_y[NMAX * FEAT];     // post-epilogue features
__device__ float g_agg[NMAX * FEAT];   // edge-aggregated output (kept zeroed between uses)
__device__ float g_as[NMAX];           // alpha_src per node
__device__ float g_ad[NMAX];           // alpha_dst per node
__device__ float g_s[NMAX];            // segment sum
__device__ float g_e[EMAX];            // per-edge exp(e)
__device__ int2  g_sd[EMAX];           // packed (src, dst)
__device__ float g_colsum[4 * FEAT];   // per-layer BN stats slots
__device__ float g_colsq[4 * FEAT];
__device__ int   g_is64;

// ---------------- startup: detect index dtype + clear BN stat slots ----------------
__global__ void start_kernel(const void* ei) {
    int t = threadIdx.x;
    if (t < 4 * FEAT) { g_colsum[t] = 0.f; g_colsq[t] = 0.f; }
    if (t < 32) {
        const long long* p = (const long long*)ei;
        int bad = 0;
        for (int i = t; i < 64; i += 32) {
            long long v = p[i];
            if (v < 0 || v >= (1LL << 31)) bad = 1;
        }
        bad = __any_sync(0xffffffffu, bad);
        if (t == 0) g_is64 = bad ? 0 : 1;
    }
}

__global__ void convert_kernel(const void* ei, int E, int ET) {
    int i = blockIdx.x * blockDim.x + threadIdx.x;
    if (i >= ET) return;
    if (i < E) {
        if (g_is64) {
            const long long* p = (const long long*)ei;
            g_sd[i] = make_int2((int)p[i], (int)p[E + i]);
        } else {
            const int* p = (const int*)ei;
            g_sd[i] = make_int2(p[i], p[E + i]);
        }
    } else {
        g_sd[i] = make_int2(i - E, i - E);
    }
}

// ---------------- fused GEMM ----------------
// h = affine(x) @ W^T ; also emits alpha_s/alpha_d per row and zeroes g_s.
// Affine (BN finalize of previous layer) computed in-block from colsum/colsq.
// Block: 256 threads, tile 64 rows x OUT cols; thread tile 4 x TN; single K chunk.
template <int IN, int OUT>
__global__ void gemm_kernel(const float* __restrict__ x, const float* __restrict__ W,
                            const float* __restrict__ gamma, const float* __restrict__ beta,
                            const float* __restrict__ colsum, const float* __restrict__ colsq,
                            float invn, int useAffine,
                            const float* __restrict__ avs, const float* __restrict__ avd,
                            float* __restrict__ h, int n) {
    const int M = 64;
    const int TN = OUT / 16;            // 4 (OUT=64) or 8 (OUT=128)
    const int SXS = M + 4;              // 68
    const int SWS = OUT + 4;            // 68 / 132
    const int V = IN / 4;               // float4 per row

    extern __shared__ __align__(16) float smem[];
    float* sSc = smem;                   // [IN]
    float* sSh = sSc + IN;               // [IN]
    float* sW  = sSh + IN;               // [IN * SWS], layout [k][o]
    float* sX  = sW + IN * SWS;          // [IN * SXS], layout [k][r]
    float* sP  = sX;                     // overlay after FMA loop: [64][16]
    float* sQ  = sX + 1024;              // [64][16]

    int tid = threadIdx.x;
    int og = tid & 15;
    int rg = tid >> 4;
    int r0 = blockIdx.x * M;

    if (useAffine) {
        for (int o = tid; o < IN; o += 256) {
            float mu = colsum[o] * invn;
            float var = colsq[o] * invn - mu * mu;
            float sc = gamma[o] * rsqrtf(var + 1e-5f);
            sSc[o] = sc;
            sSh[o] = beta[o] - mu * sc;
        }
        __syncthreads();
    }

    // load x tile [M x IN] -> sX[k][r] (transposed), with optional affine
    for (int idx = tid; idx < M * V; idx += 256) {
        int r = idx / V, vq = idx % V;
        int k = vq * 4;
        int row = r0 + r;
        float4 v = (row < n) ? *(const float4*)&x[row * IN + k] : make_float4(0.f, 0.f, 0.f, 0.f);
        if (useAffine) {
            v.x = v.x * sSc[k] + sSh[k];
            v.y = v.y * sSc[k + 1] + sSh[k + 1];
            v.z = v.z * sSc[k + 2] + sSh[k + 2];
            v.w = v.w * sSc[k + 3] + sSh[k + 3];
        }
        sX[(k + 0) * SXS + r] = v.x;
        sX[(k + 1) * SXS + r] = v.y;
        sX[(k + 2) * SXS + r] = v.z;
        sX[(k + 3) * SXS + r] = v.w;
    }
    // load W [OUT x IN] -> sW[k][o] (transposed)
    for (int idx = tid; idx < OUT * V; idx += 256) {
        int o = idx / V, vq = idx % V;
        int k = vq * 4;
        float4 w = *(const float4*)&W[o * IN + k];
        sW[(k + 0) * SWS + o] = w.x;
        sW[(k + 1) * SWS + o] = w.y;
        sW[(k + 2) * SWS + o] = w.z;
        sW[(k + 3) * SWS + o] = w.w;
    }
    __syncthreads();

    float acc[4][TN];
#pragma unroll
    for (int i = 0; i < 4; i++)
#pragma unroll
        for (int j = 0; j < TN; j++) acc[i][j] = 0.f;

#pragma unroll 4
    for (int k = 0; k < IN; k++) {
        float4 a = *(const float4*)&sX[k * SXS + rg * 4];
        const float* wb = &sW[k * SWS + og * TN];
#pragma unroll
        for (int j4 = 0; j4 < TN / 4; j4++) {
            float4 b = *(const float4*)&wb[j4 * 4];
            float bw[4] = {b.x, b.y, b.z, b.w};
#pragma unroll
            for (int jj = 0; jj < 4; jj++) {
                int j = j4 * 4 + jj;
                acc[0][j] += a.x * bw[jj];
                acc[1][j] += a.y * bw[jj];
                acc[2][j] += a.z * bw[jj];
                acc[3][j] += a.w * bw[jj];
            }
        }
    }

    // write h
#pragma unroll
    for (int i = 0; i < 4; i++) {
        int row = r0 + rg * 4 + i;
        if (row < n) {
#pragma unroll
            for (int j4 = 0; j4 < TN / 4; j4++) {
                float4 v = make_float4(acc[i][j4 * 4], acc[i][j4 * 4 + 1],
                                       acc[i][j4 * 4 + 2], acc[i][j4 * 4 + 3]);
                *(float4*)&h[row * OUT + og * TN + j4 * 4] = v;
            }
        }
    }

    // fused alpha epilogue: partial dots with a_src/a_dst, smem reduce over col groups
    float avsr[TN], avdr[TN];
#pragma unroll
    for (int j = 0; j < TN; j++) {
        avsr[j] = __ldg(&avs[og * TN + j]);
        avdr[j] = __ldg(&avd[og * TN + j]);
    }
    __syncthreads();   // sX reads done; safe to overlay sP/sQ
#pragma unroll
    for (int i = 0; i < 4; i++) {
        float ps = 0.f, pd = 0.f;
#pragma unroll
        for (int j = 0; j < TN; j++) {
            ps += acc[i][j] * avsr[j];
            pd += acc[i][j] * avdr[j];
        }
        sP[(rg * 4 + i) * 16 + og] = ps;
        sQ[(rg * 4 + i) * 16 + og] = pd;
    }
    __syncthreads();
    if (tid < M) {
        int row = r0 + tid;
        if (row < n) {
            float as = 0.f, ad = 0.f;
#pragma unroll
            for (int t = 0; t < 16; t++) {
                as += sP[tid * 16 + t];
                ad += sQ[tid * 16 + t];
            }
            g_as[row] = as;
            g_ad[row] = ad;
            g_s[row] = 0.f;
        }
    }
}

// ---------------- fused edge pass: t = exp(leaky_relu(as+ad)); segment sum ----------------
__global__ void edge12_kernel(int ET) {
    int i = blockIdx.x * blockDim.x + threadIdx.x;
    if (i >= ET) return;
    int2 sd = g_sd[i];
    float e = g_as[sd.x] + g_ad[sd.y];
    e = (e >= 0.f) ? e : 0.2f * e;
    float t = __expf(e);
    g_e[i] = t;
    atomicAdd(&g_s[sd.y], t);
}

// ---------------- edge pass 3: agg[dst] += alpha * h[src]  (vector red) ----------------
template <int OUT>
__global__ void edge3_kernel(const float* __restrict__ h, int ET) {
    const int G = OUT / 4;
    int gtid = blockIdx.x * blockDim.x + threadIdx.x;
    int i = gtid / G;
    int j = gtid % G;
    if (i >= ET) return;
    int2 sd = g_sd[i];
    float alpha = __fdividef(g_e[i], g_s[sd.y] + 1e-16f);
    const float4 hv = *(const float4*)&h[sd.x * OUT + j * 4];
    float vx = alpha * hv.x, vy = alpha * hv.y, vz = alpha * hv.z, vw = alpha * hv.w;
    float* p = &g_agg[sd.y * OUT + j * 4];
    asm volatile("red.global.add.v4.f32 [%0], {%1, %2, %3, %4};"
                 :: "l"(p), "f"(vx), "f"(vy), "f"(vz), "f"(vw) : "memory");
}

// ---------------- epilogue: y = relu(agg + b), BN column stats, zero agg ----------------
template <int OUT>
__global__ void epi_bn_kernel(const float* __restrict__ b, float* __restrict__ y,
                              float* __restrict__ colsum, float* __restrict__ colsq, int n) {
    const int T = 256;
    const int RT = T / OUT;
    const int RPB = 64;
    int o = threadIdx.x % OUT;
    int rsub = threadIdx.x / OUT;
    int r0 = blockIdx.x * RPB;
    float bo = b[o];
    float sum = 0.f, sq = 0.f;
    for (int r = rsub; r < RPB; r += RT) {
        int row = r0 + r;
        if (row >= n) break;
        float v = g_agg[row * OUT + o] + bo;
        g_agg[row * OUT + o] = 0.f;             // leave zeroed for next layer
        v = (v > 0.f) ? v : 0.f;
        y[row * OUT + o] = v;
        sum += v; sq += v * v;
    }
    __shared__ float ssum[T], ssq[T];
    ssum[threadIdx.x] = sum; ssq[threadIdx.x] = sq;
    __syncthreads();
    if (rsub == 0) {
#pragma unroll
        for (int t = 1; t < RT; t++) { sum += ssum[t * OUT + o]; sq += ssq[t * OUT + o]; }
        atomicAdd(&colsum[o], sum);
        atomicAdd(&colsq[o], sq);
    }
}

// ---------------- final: x_hat = relu(agg + b4); out = [|x - x_hat|, x_hat]; zero agg ----
__global__ void final_kernel(const float* __restrict__ x, const float* __restrict__ b4,
                             float* __restrict__ out, int n, int out_size) {
    int i = blockIdx.x * blockDim.x + threadIdx.x;
    int total = n * FEAT;
    if (i >= total) return;
    float v = g_agg[i] + b4[i & (FEAT - 1)];
    g_agg[i] = 0.f;                             // leave zeroed for next replay
    v = (v > 0.f) ? v : 0.f;
    out[i] = fabsf(x[i] - v);
    if (out_size >= 2 * total) out[total + i] = v;
}

// ---------------- host helpers ----------------
template <int IN, int OUT>
static constexpr int gemm_smem_bytes() {
    return (2 * IN + IN * (OUT + 4) + IN * (64 + 4)) * (int)sizeof(float);
}

extern "C" void kernel_launch(void* const* d_in, const int* in_sizes, int n_in,
                              void* d_out, int out_size) {
    const float* x   = (const float*)d_in[0];
    const void*  ei  = d_in[1];
    const float* W1  = (const float*)d_in[2];
    const float* a1s = (const float*)d_in[3];
    const float* a1d = (const float*)d_in[4];
    const float* b1  = (const float*)d_in[5];
    const float* g1  = (const float*)d_in[6];
    const float* be1 = (const float*)d_in[7];
    const float* W2  = (const float*)d_in[8];
    const float* a2s = (const float*)d_in[9];
    const float* a2d = (const float*)d_in[10];
    const float* b2  = (const float*)d_in[11];
    const float* g2  = (const float*)d_in[12];
    const float* be2 = (const float*)d_in[13];
    const float* W3  = (const float*)d_in[14];
    const float* a3s = (const float*)d_in[15];
    const float* a3d = (const float*)d_in[16];
    const float* b3  = (const float*)d_in[17];
    const float* g3  = (const float*)d_in[18];
    const float* be3 = (const float*)d_in[19];
    const float* W4  = (const float*)d_in[20];
    const float* a4s = (const float*)d_in[21];
    const float* a4d = (const float*)d_in[22];
    const float* b4  = (const float*)d_in[23];

    int n  = in_sizes[0] / FEAT;     // 50000
    int E  = in_sizes[1] / 2;        // 800000
    int ET = E + n;

    float *hbuf, *ybuf, *csum, *csq;
    cudaGetSymbolAddress((void**)&hbuf, g_h);
    cudaGetSymbolAddress((void**)&ybuf, g_y);
    cudaGetSymbolAddress((void**)&csum, g_colsum);
    cudaGetSymbolAddress((void**)&csq,  g_colsq);

    // opt-in >48KB dynamic smem (idempotent; not a stream op)
    cudaFuncSetAttribute(gemm_kernel<FEAT, HID>, cudaFuncAttributeMaxDynamicSharedMemorySize,
                         gemm_smem_bytes<FEAT, HID>());
    cudaFuncSetAttribute(gemm_kernel<HID, HID>, cudaFuncAttributeMaxDynamicSharedMemorySize,
                         gemm_smem_bytes<HID, HID>());
    cudaFuncSetAttribute(gemm_kernel<HID, FEAT>, cudaFuncAttributeMaxDynamicSharedMemorySize,
                         gemm_smem_bytes<HID, FEAT>());

    start_kernel<<<1, 512>>>(ei);
    convert_kernel<<<(ET + 255) / 256, 256>>>(ei, E, ET);

    float invn = 1.0f / (float)n;
    int gblk = (n + 63) / 64;

    // Layer 1: 128 -> 64
    gemm_kernel<FEAT, HID><<<gblk, 256, gemm_smem_bytes<FEAT, HID>()>>>(
        x, W1, nullptr, nullptr, nullptr, nullptr, invn, 0, a1s, a1d, hbuf, n);
    edge12_kernel<<<(ET + 255) / 256, 256>>>(ET);
    edge3_kernel<HID><<<(unsigned)(((long long)ET * (HID / 4) + 255) / 256), 256>>>(hbuf, ET);
    epi_bn_kernel<HID><<<(n + 63) / 64, 256>>>(b1, ybuf, csum + 0 * FEAT, csq + 0 * FEAT, n);

    // Layer 2: 64 -> 64 (BN1 affine folded into GEMM)
    gemm_kernel<HID, HID><<<gblk, 256, gemm_smem_bytes<HID, HID>()>>>(
        ybuf, W2, g1, be1, csum + 0 * FEAT, csq + 0 * FEAT, invn, 1, a2s, a2d, hbuf, n);
    edge12_kernel<<<(ET + 255) / 256, 256>>>(ET);
    edge3_kernel<HID><<<(unsigned)(((long long)ET * (HID / 4) + 255) / 256), 256>>>(hbuf, ET);
    epi_bn_kernel<HID><<<(n + 63) / 64, 256>>>(b2, ybuf, csum + 1 * FEAT, csq + 1 * FEAT, n);

    // Layer 3: 64 -> 64
    gemm_kernel<HID, HID><<<gblk, 256, gemm_smem_bytes<HID, HID>()>>>(
        ybuf, W3, g2, be2, csum + 1 * FEAT, csq + 1 * FEAT, invn, 1, a3s, a3d, hbuf, n);
    edge12_kernel<<<(ET + 255) / 256, 256>>>(ET);
    edge3_kernel<HID><<<(unsigned)(((long long)ET * (HID / 4) + 255) / 256), 256>>>(hbuf, ET);
    epi_bn_kernel<HID><<<(n + 63) / 64, 256>>>(b3, ybuf, csum + 2 * FEAT, csq + 2 * FEAT, n);

    // Layer 4: 64 -> 128 (no BN after)
    gemm_kernel<HID, FEAT><<<gblk, 256, gemm_smem_bytes<HID, FEAT>()>>>(
        ybuf, W4, g3, be3, csum + 2 * FEAT, csq + 2 * FEAT, invn, 1, a4s, a4d, hbuf, n);
    edge12_kernel<<<(ET + 255) / 256, 256>>>(ET);
    edge3_kernel<FEAT><<<(unsigned)(((long long)ET * (FEAT / 4) + 255) / 256), 256>>>(hbuf, ET);
    final_kernel<<<(n * FEAT + 255) / 256, 256>>>(x, b4, (float*)d_out, n, out_size);
}

// round 4
// speedup vs baseline: 1.3856x; 1.3856x over previous
#include <cuda_runtime.h>
#include <math.h>

#define FEAT 128
#define HID  64
#define NMAX 50048
#define EMAX 1048576

// ---------------- scratch (static __device__) ----------------
__device__ float g_h[NMAX * FEAT];     // post-GEMM features h
__device__ float g_y[NMAX * FEAT];     // post-epilogue features
__device__ float g_agg[NMAX * FEAT];   // edge-aggregated output
__device__ float g_as[NMAX];           // alpha_src per node
__device__ float g_ad[NMAX];           // alpha_dst per node
__device__ float g_s[NMAX];            // segment sum
__device__ float g_e[EMAX];            // per-edge exp(e)
__device__ int2  g_sd[EMAX];           // packed (src, dst)
__device__ float g_colsum[FEAT];
__device__ float g_colsq[FEAT];
__device__ float g_scale[FEAT];
__device__ float g_shift[FEAT];
__device__ int   g_is64;

// ---------------- index dtype detection + conversion ----------------
__global__ void detect_kernel(const void* ei) {
    const long long* p = (const long long*)ei;
    int bad = 0;
    for (int i = threadIdx.x; i < 64; i += 32) {
        long long v = p[i];
        if (v < 0 || v >= (1LL << 31)) bad = 1;
    }
    bad = __any_sync(0xffffffffu, bad);
    if (threadIdx.x == 0) g_is64 = bad ? 0 : 1;
}

__global__ void convert_kernel(const void* ei, int E, int ET) {
    int i = blockIdx.x * blockDim.x + threadIdx.x;
    if (i >= ET) return;
    if (i < E) {
        if (g_is64) {
            const long long* p = (const long long*)ei;
            g_sd[i] = make_int2((int)p[i], (int)p[E + i]);
        } else {
            const int* p = (const int*)ei;
            g_sd[i] = make_int2(p[i], p[E + i]);
        }
    } else {
        g_sd[i] = make_int2(i - E, i - E);
    }
}

// ---------------- per-layer init (agg zeros + BN stat slots) ----------------
__global__ void init_kernel(int total, int OUT) {
    int i = blockIdx.x * blockDim.x + threadIdx.x;
    if (i < total) g_agg[i] = 0.f;
    if (i < OUT) { g_colsum[i] = 0.f; g_colsq[i] = 0.f; }
}

// ---------------- GEMM: h = affine(x) @ W^T, fused alpha epilogue ----------------
// Block 256 threads; block tile M x OUT with M = 8192/OUT; thread tile 4 x 8.
// Also emits g_as/g_ad per row and zeroes g_s.
template <int IN, int OUT>
__global__ void gemm_kernel(const float* __restrict__ x, const float* __restrict__ W,
                            int useAffine,
                            const float* __restrict__ avs, const float* __restrict__ avd,
                            float* __restrict__ h, int n) {
    const int M = 8192 / OUT;          // 128 (OUT=64) or 64 (OUT=128)
    const int OC = OUT / 8;            // col groups: 8 or 16
    const int KC = 32;
    const int SXS = M + 4;             // 132 / 68 (mult of 4)
    const int SWS = OUT + 4;           // 68 / 132

    __shared__ __align__(16) float sSc[IN];
    __shared__ __align__(16) float sSh[IN];
    __shared__ __align__(16) float sX[KC * SXS];
    __shared__ __align__(16) float sW[KC * SWS];

    int tid = threadIdx.x;
    int og = tid % OC;
    int rg = tid / OC;
    int r0 = blockIdx.x * M;

    if (useAffine) {
        for (int o = tid; o < IN; o += 256) { sSc[o] = g_scale[o]; sSh[o] = g_shift[o]; }
        __syncthreads();
    }

    float acc[4][8];
#pragma unroll
    for (int i = 0; i < 4; i++)
#pragma unroll
        for (int j = 0; j < 8; j++) acc[i][j] = 0.f;

    for (int kc = 0; kc < IN; kc += KC) {
        // x tile [M x KC] -> sX[k][r] (transposed), optional affine
        for (int idx = tid; idx < M * (KC / 4); idx += 256) {
            int r = idx >> 3, q = idx & 7;
            int k = q * 4;
            int row = r0 + r;
            float4 v = (row < n) ? *(const float4*)&x[row * IN + kc + k]
                                 : make_float4(0.f, 0.f, 0.f, 0.f);
            if (useAffine) {
                v.x = v.x * sSc[kc + k] + sSh[kc + k];
                v.y = v.y * sSc[kc + k + 1] + sSh[kc + k + 1];
                v.z = v.z * sSc[kc + k + 2] + sSh[kc + k + 2];
                v.w = v.w * sSc[kc + k + 3] + sSh[kc + k + 3];
            }
            sX[(k + 0) * SXS + r] = v.x;
            sX[(k + 1) * SXS + r] = v.y;
            sX[(k + 2) * SXS + r] = v.z;
            sX[(k + 3) * SXS + r] = v.w;
        }
        // W tile [OUT x KC] -> sW[k][o] (transposed)
        for (int idx = tid; idx < OUT * (KC / 4); idx += 256) {
            int o = idx >> 3, q = idx & 7;
            int k = q * 4;
            float4 w = *(const float4*)&W[o * IN + kc + k];
            sW[(k + 0) * SWS + o] = w.x;
            sW[(k + 1) * SWS + o] = w.y;
            sW[(k + 2) * SWS + o] = w.z;
            sW[(k + 3) * SWS + o] = w.w;
        }
        __syncthreads();

#pragma unroll
        for (int k = 0; k < KC; k++) {
            float4 a  = *(const float4*)&sX[k * SXS + rg * 4];
            float4 b0 = *(const float4*)&sW[k * SWS + og * 8];
            float4 b1 = *(const float4*)&sW[k * SWS + og * 8 + 4];
            float av[4] = {a.x, a.y, a.z, a.w};
            float bv[8] = {b0.x, b0.y, b0.z, b0.w, b1.x, b1.y, b1.z, b1.w};
#pragma unroll
            for (int i = 0; i < 4; i++)
#pragma unroll
                for (int j = 0; j < 8; j++)
                    acc[i][j] += av[i] * bv[j];
        }
        __syncthreads();
    }

    // alpha vectors for this thread's 8 columns
    float avsr[8], avdr[8];
#pragma unroll
    for (int j = 0; j < 8; j++) {
        avsr[j] = __ldg(&avs[og * 8 + j]);
        avdr[j] = __ldg(&avd[og * 8 + j]);
    }

    // write h + alpha partials into smem overlay (sX free after final sync)
    float* sP = sX;                    // [M * OC] = 1024 floats
    float* sQ = sX + M * OC;           // [M * OC]
#pragma unroll
    for (int i = 0; i < 4; i++) {
        int rl = rg * 4 + i;
        int row = r0 + rl;
        float ps = 0.f, pd = 0.f;
#pragma unroll
        for (int j = 0; j < 8; j++) {
            ps += acc[i][j] * avsr[j];
            pd += acc[i][j] * avdr[j];
        }
        sP[rl * OC + og] = ps;
        sQ[rl * OC + og] = pd;
        if (row < n) {
            float4 v0 = make_float4(acc[i][0], acc[i][1], acc[i][2], acc[i][3]);
            float4 v1 = make_float4(acc[i][4], acc[i][5], acc[i][6], acc[i][7]);
            *(float4*)&h[row * OUT + og * 8] = v0;
            *(float4*)&h[row * OUT + og * 8 + 4] = v1;
        }
    }
    __syncthreads();
    if (tid < M) {
        int row = r0 + tid;
        if (row < n) {
            float as = 0.f, ad = 0.f;
#pragma unroll
            for (int t = 0; t < OC; t++) {
                as += sP[tid * OC + t];
                ad += sQ[tid * OC + t];
            }
            g_as[row] = as;
            g_ad[row] = ad;
            g_s[row] = 0.f;
        }
    }
}

// ---------------- fused edge pass: t = exp(leaky_relu(as+ad)); segment sum ----------------
__global__ void edge12_kernel(int ET) {
    int i = blockIdx.x * blockDim.x + threadIdx.x;
    if (i >= ET) return;
    int2 sd = g_sd[i];
    float e = g_as[sd.x] + g_ad[sd.y];
    e = (e >= 0.f) ? e : 0.2f * e;
    float t = __expf(e);
    g_e[i] = t;
    atomicAdd(&g_s[sd.y], t);
}

// ---------------- edge pass 3: agg[dst] += alpha * h[src]  (vector red) ----------------
template <int OUT>
__global__ void edge3_kernel(const float* __restrict__ h, int ET) {
    const int G = OUT / 4;
    int gtid = blockIdx.x * blockDim.x + threadIdx.x;
    int i = gtid / G;
    int j = gtid % G;
    if (i >= ET) return;
    int2 sd = g_sd[i];
    float alpha = __fdividef(g_e[i], g_s[sd.y] + 1e-16f);
    const float4 hv = *(const float4*)&h[sd.x * OUT + j * 4];
    float vx = alpha * hv.x, vy = alpha * hv.y, vz = alpha * hv.z, vw = alpha * hv.w;
    float* p = &g_agg[sd.y * OUT + j * 4];
    asm volatile("red.global.add.v4.f32 [%0], {%1, %2, %3, %4};"
                 :: "l"(p), "f"(vx), "f"(vy), "f"(vz), "f"(vw) : "memory");
}

// ---------------- epilogue: y = relu(agg + b), accumulate BN column stats ----------------
template <int OUT>
__global__ void epi_bn_kernel(const float* __restrict__ b, float* __restrict__ y, int n) {
    const int T = 256;
    const int RT = T / OUT;
    const int RPB = 64;
    int o = threadIdx.x % OUT;
    int rsub = threadIdx.x / OUT;
    int r0 = blockIdx.x * RPB;
    float bo = b[o];
    float sum = 0.f, sq = 0.f;
    for (int r = rsub; r < RPB; r += RT) {
        int row = r0 + r;
        if (row >= n) break;
        float v = g_agg[row * OUT + o] + bo;
        v = (v > 0.f) ? v : 0.f;
        y[row * OUT + o] = v;
        sum += v; sq += v * v;
    }
    __shared__ float ssum[T], ssq[T];
    ssum[threadIdx.x] = sum; ssq[threadIdx.x] = sq;
    __syncthreads();
    if (rsub == 0) {
#pragma unroll
        for (int t = 1; t < RT; t++) { sum += ssum[t * OUT + o]; sq += ssq[t * OUT + o]; }
        atomicAdd(&g_colsum[o], sum);
        atomicAdd(&g_colsq[o], sq);
    }
}

// ---------------- BN finalize ----------------
__global__ void bnfin_kernel(const float* __restrict__ g, const float* __restrict__ be,
                             int OUT, float invn) {
    int o = threadIdx.x;
    if (o >= OUT) return;
    float mu = g_colsum[o] * invn;
    float var = g_colsq[o] * invn - mu * mu;
    float sc = g[o] * rsqrtf(var + 1e-5f);
    g_scale[o] = sc;
    g_shift[o] = be[o] - mu * sc;
}

// ---------------- final: x_hat = relu(agg + b4); out = [|x - x_hat|, x_hat] ----------------
__global__ void final_kernel(const float* __restrict__ x, const float* __restrict__ b4,
                             float* __restrict__ out, int n, int out_size) {
    int i = blockIdx.x * blockDim.x + threadIdx.x;
    int total = n * FEAT;
    if (i >= total) return;
    float v = g_agg[i] + b4[i & (FEAT - 1)];
    v = (v > 0.f) ? v : 0.f;
    out[i] = fabsf(x[i] - v);
    if (out_size >= 2 * total) out[total + i] = v;
}

// ---------------- host-side layer driver ----------------
template <int IN, int OUT>
static void run_gat(const float* xin, int useAffine, const float* W,
                    const float* avs, const float* avd,
                    float* hbuf, int n, int ET) {
    const int M = 8192 / OUT;
    int initTotal = n * OUT;
    init_kernel<<<(initTotal + 255) / 256, 256>>>(initTotal, OUT);
    gemm_kernel<IN, OUT><<<(n + M - 1) / M, 256>>>(xin, W, useAffine, avs, avd, hbuf, n);
    edge12_kernel<<<(ET + 255) / 256, 256>>>(ET);
    long long work = (long long)ET * (OUT / 4);
    edge3_kernel<OUT><<<(unsigned)((work + 255) / 256), 256>>>(hbuf, ET);
}

extern "C" void kernel_launch(void* const* d_in, const int* in_sizes, int n_in,
                              void* d_out, int out_size) {
    const float* x   = (const float*)d_in[0];
    const void*  ei  = d_in[1];
    const float* W1  = (const float*)d_in[2];
    const float* a1s = (const float*)d_in[3];
    const float* a1d = (const float*)d_in[4];
    const float* b1  = (const float*)d_in[5];
    const float* g1  = (const float*)d_in[6];
    const float* be1 = (const float*)d_in[7];
    const float* W2  = (const float*)d_in[8];
    const float* a2s = (const float*)d_in[9];
    const float* a2d = (const float*)d_in[10];
    const float* b2  = (const float*)d_in[11];
    const float* g2  = (const float*)d_in[12];
    const float* be2 = (const float*)d_in[13];
    const float* W3  = (const float*)d_in[14];
    const float* a3s = (const float*)d_in[15];
    const float* a3d = (const float*)d_in[16];
    const float* b3  = (const float*)d_in[17];
    const float* g3  = (const float*)d_in[18];
    const float* be3 = (const float*)d_in[19];
    const float* W4  = (const float*)d_in[20];
    const float* a4s = (const float*)d_in[21];
    const float* a4d = (const float*)d_in[22];
    const float* b4  = (const float*)d_in[23];

    int n  = in_sizes[0] / FEAT;     // 50000
    int E  = in_sizes[1] / 2;        // 800000
    int ET = E + n;

    float *hbuf, *ybuf;
    cudaGetSymbolAddress((void**)&hbuf, g_h);
    cudaGetSymbolAddress((void**)&ybuf, g_y);

    detect_kernel<<<1, 32>>>(ei);
    convert_kernel<<<(ET + 255) / 256, 256>>>(ei, E, ET);

    float invn = 1.0f / (float)n;

    // Layer 1: 128 -> 64, relu, BN
    run_gat<FEAT, HID>(x, 0, W1, a1s, a1d, hbuf, n, ET);
    epi_bn_kernel<HID><<<(n + 63) / 64, 256>>>(b1, ybuf, n);
    bnfin_kernel<<<1, HID>>>(g1, be1, HID, invn);

    // Layer 2: 64 -> 64, relu, BN (BN1 affine folded into GEMM x-load)
    run_gat<HID, HID>(ybuf, 1, W2, a2s, a2d, hbuf, n, ET);
    epi_bn_kernel<HID><<<(n + 63) / 64, 256>>>(b2, ybuf, n);
    bnfin_kernel<<<1, HID>>>(g2, be2, HID, invn);

    // Layer 3: 64 -> 64, relu, BN
    run_gat<HID, HID>(ybuf, 1, W3, a3s, a3d, hbuf, n, ET);
    epi_bn_kernel<HID><<<(n + 63) / 64, 256>>>(b3, ybuf, n);
    bnfin_kernel<<<1, HID>>>(g3, be3, HID, invn);

    // Layer 4: 64 -> 128, relu (no BN)
    run_gat<HID, FEAT>(ybuf, 1, W4, a4s, a4d, hbuf, n, ET);
    final_kernel<<<(n * FEAT + 255) / 256, 256>>>(x, b4, (float*)d_out, n, out_size);
}